// round 1
// baseline (speedup 1.0000x reference)
#include <cuda_runtime.h>
#include <math.h>

#define B_SZ 32768
#define H_SZ 896
#define S_SZ 448
#define Q_SZ 256
#define H3   (3 * H_SZ)   // 2688
#define S3   (3 * S_SZ)   // 1344

// Scratch (static device globals — allowed; no runtime allocation).
__device__ float g_R[(size_t)B_SZ * H3];      // 352 MB: gate pre-activations
__device__ float g_t[(size_t)B_SZ * S_SZ];    // 58.7 MB: relu(h @ W_O{1,3} + b)

// ---------------------------------------------------------------------------
// Classic 128x128x8 register-blocked SGEMM, 256 threads, 8x8 microtile.
// C[M,N] = op(A[M,K] @ B[K,N] + bias), A row stride = lda (lets us read the
// coarse/fine halves of `hidden` in place).
// Alignment contract (holds for every call here): lda, ldb, ldc, N, K all
// multiples of 4; base pointers 256B-aligned -> float4 loads are safe.
// ---------------------------------------------------------------------------
template<bool RELU, bool NGUARD>
__global__ __launch_bounds__(256)
void sgemm_kernel(const float* __restrict__ A, const float* __restrict__ Bm,
                  const float* __restrict__ bias, float* __restrict__ C,
                  int M, int N, int K, int lda, int ldb, int ldc)
{
    __shared__ float As[8][128];
    __shared__ float Bs[8][128];

    const int tid = threadIdx.x;
    const int m0 = blockIdx.y * 128;
    const int n0 = blockIdx.x * 128;

    const int tx = tid & 15;        // 0..15 -> N
    const int ty = tid >> 4;        // 0..15 -> M

    // load mapping
    const int a_m = tid >> 1;          // 0..127
    const int a_k = (tid & 1) * 4;     // 0 or 4
    const int b_k = tid >> 5;          // 0..7
    const int b_n = (tid & 31) * 4;    // 0..124

    float acc[8][8];
#pragma unroll
    for (int i = 0; i < 8; i++)
#pragma unroll
        for (int j = 0; j < 8; j++) acc[i][j] = 0.f;

    for (int k0 = 0; k0 < K; k0 += 8) {
        // A tile: 128 rows x 8 k (stored transposed As[k][m])
        {
            const float4 av = *reinterpret_cast<const float4*>(
                A + (size_t)(m0 + a_m) * lda + (k0 + a_k));
            As[a_k + 0][a_m] = av.x;
            As[a_k + 1][a_m] = av.y;
            As[a_k + 2][a_m] = av.z;
            As[a_k + 3][a_m] = av.w;
        }
        // B tile: 8 k x 128 n
        {
            float4 bv = make_float4(0.f, 0.f, 0.f, 0.f);
            if (!NGUARD || (n0 + b_n) < N)
                bv = *reinterpret_cast<const float4*>(
                    Bm + (size_t)(k0 + b_k) * ldb + (n0 + b_n));
            *reinterpret_cast<float4*>(&Bs[b_k][b_n]) = bv;
        }
        __syncthreads();

#pragma unroll
        for (int k = 0; k < 8; k++) {
            float a_frag[8], b_frag[8];
#pragma unroll
            for (int i = 0; i < 8; i++) a_frag[i] = As[k][ty * 8 + i];
#pragma unroll
            for (int j = 0; j < 8; j++) b_frag[j] = Bs[k][tx * 8 + j];
#pragma unroll
            for (int i = 0; i < 8; i++)
#pragma unroll
                for (int j = 0; j < 8; j++)
                    acc[i][j] = fmaf(a_frag[i], b_frag[j], acc[i][j]);
        }
        __syncthreads();
    }

    // epilogue
#pragma unroll
    for (int i = 0; i < 8; i++) {
        const size_t m = (size_t)(m0 + ty * 8 + i);
#pragma unroll
        for (int j = 0; j < 8; j++) {
            const int n = n0 + tx * 8 + j;
            if (!NGUARD || n < N) {
                float v = acc[i][j];
                if (bias) v += bias[n];
                if (RELU) v = fmaxf(v, 0.f);
                C[m * ldc + n] = v;
            }
        }
    }
}

// ---------------------------------------------------------------------------
// Fused gates: tiny input projections (K=2 / K=3) inlined, then GRU-style
// update. Reads g_R, writes hidden into d_out.
// ---------------------------------------------------------------------------
__global__ __launch_bounds__(256)
void gates_kernel(const float* __restrict__ R,
                  const float* __restrict__ prev_y,
                  const float* __restrict__ cc,
                  const float* __restrict__ prev_hidden,
                  const float* __restrict__ W_Ic,
                  const float* __restrict__ W_If,
                  const float* __restrict__ bu,
                  const float* __restrict__ br,
                  const float* __restrict__ be,
                  float* __restrict__ hidden_out)
{
    const size_t idx = (size_t)blockIdx.x * blockDim.x + threadIdx.x;
    if (idx >= (size_t)B_SZ * H_SZ) return;
    const int b = (int)(idx / H_SZ);
    const int h = (int)(idx % H_SZ);

    const float y0 = prev_y[2 * b];
    const float y1 = prev_y[2 * b + 1];

    float Iu, Ir, Ie;
    if (h < S_SZ) {
        // coarse half: fine_in = (y0, y1)
        Iu = fmaf(y0, W_Ic[h],              y1 * W_Ic[S3 + h]);
        Ir = fmaf(y0, W_Ic[S_SZ + h],       y1 * W_Ic[S3 + S_SZ + h]);
        Ie = fmaf(y0, W_Ic[2 * S_SZ + h],   y1 * W_Ic[S3 + 2 * S_SZ + h]);
    } else {
        const int j = h - S_SZ;
        const float c = cc[b];
        Iu = fmaf(y0, W_If[j],            fmaf(y1, W_If[S3 + j],            c * W_If[2 * S3 + j]));
        Ir = fmaf(y0, W_If[S_SZ + j],     fmaf(y1, W_If[S3 + S_SZ + j],     c * W_If[2 * S3 + S_SZ + j]));
        Ie = fmaf(y0, W_If[2 * S_SZ + j], fmaf(y1, W_If[S3 + 2 * S_SZ + j], c * W_If[2 * S3 + 2 * S_SZ + j]));
    }

    const size_t rb = (size_t)b * H3;
    const float Ru = R[rb + h];
    const float Rr = R[rb + H_SZ + h];
    const float Re = R[rb + 2 * H_SZ + h];

    const float u = 1.f / (1.f + __expf(-(Ru + Iu + bu[h])));
    const float r = 1.f / (1.f + __expf(-(Rr + Ir + br[h])));
    const float e = tanhf(fmaf(r, Re, Ie + be[h]));

    const float ph = prev_hidden[idx];
    hidden_out[idx] = fmaf(u, ph - e, e);   // u*ph + (1-u)*e
}

// ---------------------------------------------------------------------------
extern "C" void kernel_launch(void* const* d_in, const int* in_sizes, int n_in,
                              void* d_out, int out_size)
{
    const float* prev_y         = (const float*)d_in[0];
    const float* prev_hidden    = (const float*)d_in[1];
    const float* current_coarse = (const float*)d_in[2];
    const float* W_R            = (const float*)d_in[3];
    const float* W_Ic           = (const float*)d_in[4];
    const float* W_If           = (const float*)d_in[5];
    const float* W_O1           = (const float*)d_in[6];
    const float* b_O1           = (const float*)d_in[7];
    const float* W_O2           = (const float*)d_in[8];
    const float* b_O2           = (const float*)d_in[9];
    const float* W_O3           = (const float*)d_in[10];
    const float* b_O3           = (const float*)d_in[11];
    const float* W_O4           = (const float*)d_in[12];
    const float* b_O4           = (const float*)d_in[13];
    const float* bias_u         = (const float*)d_in[14];
    const float* bias_r         = (const float*)d_in[15];
    const float* bias_e         = (const float*)d_in[16];

    float* out        = (float*)d_out;
    float* out_coarse = out;                                  // [B, Q]
    float* out_fine   = out + (size_t)B_SZ * Q_SZ;            // [B, Q]
    float* hidden     = out + 2 * (size_t)B_SZ * Q_SZ;        // [B, H]

    float* R;  cudaGetSymbolAddress((void**)&R, g_R);
    float* t;  cudaGetSymbolAddress((void**)&t, g_t);

    const dim3 blk(256);

    // 1) R = prev_hidden @ W_R   [32768 x 2688], K=896
    sgemm_kernel<false, false><<<dim3(H3 / 128, B_SZ / 128), blk>>>(
        prev_hidden, W_R, nullptr, R, B_SZ, H3, H_SZ, H_SZ, H3, H3);

    // 2) gates -> hidden (written straight into d_out)
    {
        const size_t total = (size_t)B_SZ * H_SZ;
        gates_kernel<<<(unsigned)((total + 255) / 256), blk>>>(
            R, prev_y, current_coarse, prev_hidden,
            W_Ic, W_If, bias_u, bias_r, bias_e, hidden);
    }

    // 3) coarse head: t = relu(h_c @ W_O1 + b_O1); out_coarse = t @ W_O2 + b_O2
    sgemm_kernel<true, true><<<dim3((S_SZ + 127) / 128, B_SZ / 128), blk>>>(
        hidden, W_O1, b_O1, t, B_SZ, S_SZ, S_SZ, H_SZ, S_SZ, S_SZ);
    sgemm_kernel<false, false><<<dim3(Q_SZ / 128, B_SZ / 128), blk>>>(
        t, W_O2, b_O2, out_coarse, B_SZ, Q_SZ, S_SZ, S_SZ, Q_SZ, Q_SZ);

    // 4) fine head: t = relu(h_f @ W_O3 + b_O3); out_fine = t @ W_O4 + b_O4
    sgemm_kernel<true, true><<<dim3((S_SZ + 127) / 128, B_SZ / 128), blk>>>(
        hidden + S_SZ, W_O3, b_O3, t, B_SZ, S_SZ, S_SZ, H_SZ, S_SZ, S_SZ);
    sgemm_kernel<false, false><<<dim3(Q_SZ / 128, B_SZ / 128), blk>>>(
        t, W_O4, b_O4, out_fine, B_SZ, Q_SZ, S_SZ, S_SZ, Q_SZ, Q_SZ);
}

// round 3
// speedup vs baseline: 2.0170x; 2.0170x over previous
#include <cuda_runtime.h>
#include <cuda_bf16.h>
#include <math.h>
#include <stdint.h>

#define B_SZ 32768
#define H_SZ 896
#define S_SZ 448
#define Q_SZ 256
#define H3   2688
#define S3   1344
#define SPAD 512

// ---------------- scratch (device globals; no runtime allocation) ----------
__device__ float          g_R[(size_t)B_SZ * H3];
__device__ __nv_bfloat16  g_Ahi[(size_t)B_SZ * H_SZ];
__device__ __nv_bfloat16  g_Alo[(size_t)B_SZ * H_SZ];
__device__ __nv_bfloat16  g_Thi[2 * (size_t)B_SZ * SPAD];
__device__ __nv_bfloat16  g_Tlo[2 * (size_t)B_SZ * SPAD];

#define OWR 0
#define OW1 (OWR + H3 * H_SZ)
#define OW2 (OW1 + SPAD * S_SZ)
#define OW3 (OW2 + Q_SZ * S_SZ)
#define OW4 (OW3 + SPAD * S_SZ)
#define W_TOTAL (OW4 + Q_SZ * S_SZ)
__device__ __nv_bfloat16  g_Whi[W_TOTAL];
__device__ __nv_bfloat16  g_Wlo[W_TOTAL];

// ---------------- helpers ---------------------------------------------------
__device__ __forceinline__ uint32_t smem_u32(const void* p) {
    uint32_t a;
    asm("{ .reg .u64 t; cvta.to.shared.u64 t, %1; cvt.u32.u64 %0, t; }"
        : "=r"(a) : "l"(p));
    return a;
}
__device__ __forceinline__ void cpa16(uint32_t dst, const void* src) {
    asm volatile("cp.async.cg.shared.global [%0], [%1], 16;\n" :: "r"(dst), "l"(src));
}
__device__ __forceinline__ void ldm_x4(uint32_t* r, uint32_t addr) {
    asm volatile("ldmatrix.sync.aligned.m8n8.x4.shared.b16 {%0,%1,%2,%3}, [%4];"
        : "=r"(r[0]), "=r"(r[1]), "=r"(r[2]), "=r"(r[3]) : "r"(addr));
}
#define MMA(d, a, b) \
    asm volatile("mma.sync.aligned.m16n8k16.row.col.f32.bf16.bf16.f32 " \
        "{%0,%1,%2,%3}, {%4,%5,%6,%7}, {%8,%9}, {%0,%1,%2,%3};" \
        : "+f"((d)[0]), "+f"((d)[1]), "+f"((d)[2]), "+f"((d)[3]) \
        : "r"((a)[0]), "r"((a)[1]), "r"((a)[2]), "r"((a)[3]), \
          "r"((b)[0]), "r"((b)[1]))

// SMEM tile: 128 rows x 32 bf16 cols, row pitch 80 B (64 data + 16 pad).
// Pitch 80 => 8-row ldmatrix touches all 32 banks exactly once (20-word stride).
#define T_PITCH 80
#define T_BYTES (128 * T_PITCH)          // 10240 per tile
#define ST_BYTES (4 * T_BYTES)           // Ahi,Alo,Bhi,Blo per stage
#define SM_TOT   (2 * ST_BYTES)          // 81920

// ---------------- split-bf16 HMMA GEMM --------------------------------------
// C = A @ B^T.  A=[M,K] (hi,lo) row-major, B^T=[N,K] (hi,lo) row-major.
// EPI 0: fp32 (no bias)  1: bias+relu -> split bf16  2: bias -> fp32
template<int EPI>
__global__ __launch_bounds__(256)
void gemm_hmma(const __nv_bfloat16* __restrict__ Ahi,
               const __nv_bfloat16* __restrict__ Alo, int lda,
               const __nv_bfloat16* __restrict__ Bhi,
               const __nv_bfloat16* __restrict__ Blo, int ldb,
               const float* __restrict__ bias,
               float* __restrict__ outF,
               __nv_bfloat16* __restrict__ outHi,
               __nv_bfloat16* __restrict__ outLo,
               int ldc, int K, int Nreal)
{
    extern __shared__ char smem[];
    const uint32_t smb = smem_u32(smem);
    const int tid  = threadIdx.x;
    const int wid  = tid >> 5;
    const int lane = tid & 31;
    const int m0 = blockIdx.y * 128;
    const int n0 = blockIdx.x * 128;

    const int wmb = (wid & 1) * 64;   // warp m base (2 warps in m)
    const int wnb = (wid >> 1) * 32;  // warp n base (4 warps in n)

    // cp.async mapping: 2 x 16B per tile per thread
    const int ld_row0 = tid >> 1;                // 0..127
    const int ld_ch0  = (tid & 1) * 2;           // 0 or 2 (16B chunks)
    const int g_col0  = ld_ch0 * 8;              // bf16 col of first 16B

    // ldmatrix lane mapping
    const int j  = lane >> 3;     // matrix index 0..3
    const int r8 = lane & 7;      // row within 8x8

    float acc[4][4][4];
#pragma unroll
    for (int mt = 0; mt < 4; mt++)
#pragma unroll
        for (int nt = 0; nt < 4; nt++)
#pragma unroll
            for (int i = 0; i < 4; i++) acc[mt][nt][i] = 0.f;

    const int nc = K >> 5;    // K/32 chunks

    auto load_stage = [&](int c, int st) {
        const int k0 = c << 5;
        const uint32_t sb = smb + st * ST_BYTES;
        const uint32_t so = ld_row0 * T_PITCH + ld_ch0 * 16;
        const __nv_bfloat16* gah = Ahi + (size_t)(m0 + ld_row0) * lda + k0 + g_col0;
        const __nv_bfloat16* gal = Alo + (size_t)(m0 + ld_row0) * lda + k0 + g_col0;
        const __nv_bfloat16* gbh = Bhi + (size_t)(n0 + ld_row0) * ldb + k0 + g_col0;
        const __nv_bfloat16* gbl = Blo + (size_t)(n0 + ld_row0) * ldb + k0 + g_col0;
        cpa16(sb + 0 * T_BYTES + so,      gah);
        cpa16(sb + 0 * T_BYTES + so + 16, gah + 8);
        cpa16(sb + 1 * T_BYTES + so,      gal);
        cpa16(sb + 1 * T_BYTES + so + 16, gal + 8);
        cpa16(sb + 2 * T_BYTES + so,      gbh);
        cpa16(sb + 2 * T_BYTES + so + 16, gbh + 8);
        cpa16(sb + 3 * T_BYTES + so,      gbl);
        cpa16(sb + 3 * T_BYTES + so + 16, gbl + 8);
        asm volatile("cp.async.commit_group;\n" ::: "memory");
    };

    load_stage(0, 0);

    // per-thread ldmatrix address components (within a tile)
    const uint32_t a_row_off = (uint32_t)(wmb + (j & 1) * 8 + r8) * T_PITCH + ((j >> 1) * 8) * 2;
    const uint32_t b_row_off = (uint32_t)(wnb + (j >> 1) * 8 + r8) * T_PITCH + ((j & 1) * 8) * 2;

    for (int c = 0; c < nc; c++) {
        if (c + 1 < nc) {
            load_stage(c + 1, (c + 1) & 1);
            asm volatile("cp.async.wait_group 1;\n" ::: "memory");
        } else {
            asm volatile("cp.async.wait_group 0;\n" ::: "memory");
        }
        __syncthreads();

        const uint32_t sb = smb + (c & 1) * ST_BYTES;
        const uint32_t sAh = sb;
        const uint32_t sAl = sb + T_BYTES;
        const uint32_t sBh = sb + 2 * T_BYTES;
        const uint32_t sBl = sb + 3 * T_BYTES;

#pragma unroll
        for (int ks = 0; ks < 2; ks++) {
            const uint32_t kso = ks * 32;   // 16 bf16 = 32B

            uint32_t ah[4][4], bh[2][4];
#pragma unroll
            for (int mt = 0; mt < 4; mt++)
                ldm_x4(ah[mt], sAh + a_row_off + (uint32_t)mt * 16 * T_PITCH + kso);
#pragma unroll
            for (int p = 0; p < 2; p++)
                ldm_x4(bh[p], sBh + b_row_off + (uint32_t)p * 16 * T_PITCH + kso);

#pragma unroll
            for (int mt = 0; mt < 4; mt++)
#pragma unroll
                for (int nt = 0; nt < 4; nt++)
                    MMA(acc[mt][nt], ah[mt], &bh[nt >> 1][(nt & 1) * 2]);

            uint32_t al[4][4];
#pragma unroll
            for (int mt = 0; mt < 4; mt++)
                ldm_x4(al[mt], sAl + a_row_off + (uint32_t)mt * 16 * T_PITCH + kso);
#pragma unroll
            for (int mt = 0; mt < 4; mt++)
#pragma unroll
                for (int nt = 0; nt < 4; nt++)
                    MMA(acc[mt][nt], al[mt], &bh[nt >> 1][(nt & 1) * 2]);

            uint32_t bl[2][4];
#pragma unroll
            for (int p = 0; p < 2; p++)
                ldm_x4(bl[p], sBl + b_row_off + (uint32_t)p * 16 * T_PITCH + kso);
#pragma unroll
            for (int mt = 0; mt < 4; mt++)
#pragma unroll
                for (int nt = 0; nt < 4; nt++)
                    MMA(acc[mt][nt], ah[mt], &bl[nt >> 1][(nt & 1) * 2]);
        }
        __syncthreads();
    }

    // ---------------- epilogue ----------------
    const int g  = lane >> 2;
    const int tq = lane & 3;
#pragma unroll
    for (int mt = 0; mt < 4; mt++) {
#pragma unroll
        for (int half = 0; half < 2; half++) {
            const size_t m = (size_t)(m0 + wmb + mt * 16 + g + half * 8);
#pragma unroll
            for (int nt = 0; nt < 4; nt++) {
                const int n = n0 + wnb + nt * 8 + 2 * tq;
                if (n < Nreal) {
                    float v0 = acc[mt][nt][half * 2 + 0];
                    float v1 = acc[mt][nt][half * 2 + 1];
                    if (EPI != 0) { v0 += bias[n]; v1 += bias[n + 1]; }
                    if (EPI == 1) {
                        v0 = fmaxf(v0, 0.f); v1 = fmaxf(v1, 0.f);
                        __nv_bfloat16 h0 = __float2bfloat16(v0);
                        __nv_bfloat16 h1 = __float2bfloat16(v1);
                        __nv_bfloat162* ph = reinterpret_cast<__nv_bfloat162*>(outHi + m * ldc + n);
                        __nv_bfloat162* pl = reinterpret_cast<__nv_bfloat162*>(outLo + m * ldc + n);
                        *ph = __nv_bfloat162(h0, h1);
                        *pl = __nv_bfloat162(__float2bfloat16(v0 - __bfloat162float(h0)),
                                             __float2bfloat16(v1 - __bfloat162float(h1)));
                    } else {
                        float2* pf = reinterpret_cast<float2*>(outF + m * ldc + n);
                        *pf = make_float2(v0, v1);
                    }
                }
            }
        }
    }
}

// ---------------- conversion kernels ----------------------------------------
__global__ void k_split(const float* __restrict__ in,
                        __nv_bfloat16* __restrict__ hi,
                        __nv_bfloat16* __restrict__ lo, size_t n)
{
    size_t i = (size_t)blockIdx.x * blockDim.x + threadIdx.x;
    if (i < n) {
        float f = in[i];
        __nv_bfloat16 h = __float2bfloat16(f);
        hi[i] = h;
        lo[i] = __float2bfloat16(f - __bfloat162float(h));
    }
}

__global__ void k_splitT(const float* __restrict__ W,
                         __nv_bfloat16* __restrict__ hiT,
                         __nv_bfloat16* __restrict__ loT,
                         int K, int N, int Npad)
{
    int i = blockIdx.x * blockDim.x + threadIdx.x;
    if (i < Npad * K) {
        int n = i / K, k = i % K;
        float f = (n < N) ? W[(size_t)k * N + n] : 0.f;
        __nv_bfloat16 h = __float2bfloat16(f);
        hiT[i] = h;
        loT[i] = __float2bfloat16(f - __bfloat162float(h));
    }
}

// ---------------- fused gates -------------------------------------------------
__global__ __launch_bounds__(256)
void gates_kernel(const float* __restrict__ R,
                  const float* __restrict__ prev_y,
                  const float* __restrict__ cc,
                  const float* __restrict__ prev_hidden,
                  const float* __restrict__ W_Ic,
                  const float* __restrict__ W_If,
                  const float* __restrict__ bu,
                  const float* __restrict__ br,
                  const float* __restrict__ be,
                  float* __restrict__ hidden_out)
{
    const size_t idx = (size_t)blockIdx.x * blockDim.x + threadIdx.x;
    if (idx >= (size_t)B_SZ * H_SZ) return;
    const int b = (int)(idx / H_SZ);
    const int h = (int)(idx % H_SZ);

    const float y0 = prev_y[2 * b];
    const float y1 = prev_y[2 * b + 1];

    float Iu, Ir, Ie;
    if (h < S_SZ) {
        Iu = fmaf(y0, W_Ic[h],            y1 * W_Ic[S3 + h]);
        Ir = fmaf(y0, W_Ic[S_SZ + h],     y1 * W_Ic[S3 + S_SZ + h]);
        Ie = fmaf(y0, W_Ic[2 * S_SZ + h], y1 * W_Ic[S3 + 2 * S_SZ + h]);
    } else {
        const int jj = h - S_SZ;
        const float c = cc[b];
        Iu = fmaf(y0, W_If[jj],            fmaf(y1, W_If[S3 + jj],            c * W_If[2 * S3 + jj]));
        Ir = fmaf(y0, W_If[S_SZ + jj],     fmaf(y1, W_If[S3 + S_SZ + jj],     c * W_If[2 * S3 + S_SZ + jj]));
        Ie = fmaf(y0, W_If[2 * S_SZ + jj], fmaf(y1, W_If[S3 + 2 * S_SZ + jj], c * W_If[2 * S3 + 2 * S_SZ + jj]));
    }

    const size_t rb = (size_t)b * H3;
    const float Ru = R[rb + h];
    const float Rr = R[rb + H_SZ + h];
    const float Re = R[rb + 2 * H_SZ + h];

    const float u = 1.f / (1.f + __expf(-(Ru + Iu + bu[h])));
    const float r = 1.f / (1.f + __expf(-(Rr + Ir + br[h])));
    const float e = tanhf(fmaf(r, Re, Ie + be[h]));

    const float ph = prev_hidden[idx];
    hidden_out[idx] = fmaf(u, ph - e, e);
}

// ---------------- launch -------------------------------------------------------
extern "C" void kernel_launch(void* const* d_in, const int* in_sizes, int n_in,
                              void* d_out, int out_size)
{
    const float* prev_y         = (const float*)d_in[0];
    const float* prev_hidden    = (const float*)d_in[1];
    const float* current_coarse = (const float*)d_in[2];
    const float* W_R            = (const float*)d_in[3];
    const float* W_Ic           = (const float*)d_in[4];
    const float* W_If           = (const float*)d_in[5];
    const float* W_O1           = (const float*)d_in[6];
    const float* b_O1           = (const float*)d_in[7];
    const float* W_O2           = (const float*)d_in[8];
    const float* b_O2           = (const float*)d_in[9];
    const float* W_O3           = (const float*)d_in[10];
    const float* b_O3           = (const float*)d_in[11];
    const float* W_O4           = (const float*)d_in[12];
    const float* b_O4           = (const float*)d_in[13];
    const float* bias_u         = (const float*)d_in[14];
    const float* bias_r         = (const float*)d_in[15];
    const float* bias_e         = (const float*)d_in[16];

    float* out        = (float*)d_out;
    float* out_coarse = out;
    float* out_fine   = out + (size_t)B_SZ * Q_SZ;
    float* hidden     = out + 2 * (size_t)B_SZ * Q_SZ;

    float*         R;   cudaGetSymbolAddress((void**)&R,   g_R);
    __nv_bfloat16* Ahi; cudaGetSymbolAddress((void**)&Ahi, g_Ahi);
    __nv_bfloat16* Alo; cudaGetSymbolAddress((void**)&Alo, g_Alo);
    __nv_bfloat16* Thi; cudaGetSymbolAddress((void**)&Thi, g_Thi);
    __nv_bfloat16* Tlo; cudaGetSymbolAddress((void**)&Tlo, g_Tlo);
    __nv_bfloat16* Whi; cudaGetSymbolAddress((void**)&Whi, g_Whi);
    __nv_bfloat16* Wlo; cudaGetSymbolAddress((void**)&Wlo, g_Wlo);

    cudaFuncSetAttribute(gemm_hmma<0>, cudaFuncAttributeMaxDynamicSharedMemorySize, SM_TOT);
    cudaFuncSetAttribute(gemm_hmma<1>, cudaFuncAttributeMaxDynamicSharedMemorySize, SM_TOT);
    cudaFuncSetAttribute(gemm_hmma<2>, cudaFuncAttributeMaxDynamicSharedMemorySize, SM_TOT);

    const size_t TOFF = (size_t)B_SZ * SPAD;

    // 1) weight conversion + transpose (bf16 hi/lo)
    {
        int n;
        n = H3 * H_SZ;    k_splitT<<<(n + 255) / 256, 256>>>(W_R,  Whi + OWR, Wlo + OWR, H_SZ, H3,   H3);
        n = SPAD * S_SZ;  k_splitT<<<(n + 255) / 256, 256>>>(W_O1, Whi + OW1, Wlo + OW1, S_SZ, S_SZ, SPAD);
        n = Q_SZ * S_SZ;  k_splitT<<<(n + 255) / 256, 256>>>(W_O2, Whi + OW2, Wlo + OW2, S_SZ, Q_SZ, Q_SZ);
        n = SPAD * S_SZ;  k_splitT<<<(n + 255) / 256, 256>>>(W_O3, Whi + OW3, Wlo + OW3, S_SZ, S_SZ, SPAD);
        n = Q_SZ * S_SZ;  k_splitT<<<(n + 255) / 256, 256>>>(W_O4, Whi + OW4, Wlo + OW4, S_SZ, Q_SZ, Q_SZ);
    }

    // 2) prev_hidden -> bf16 hi/lo
    {
        size_t n = (size_t)B_SZ * H_SZ;
        k_split<<<(unsigned)((n + 255) / 256), 256>>>(prev_hidden, Ahi, Alo, n);
    }

    // 3) R = prev_hidden @ W_R
    gemm_hmma<0><<<dim3(H3 / 128, B_SZ / 128), 256, SM_TOT>>>(
        Ahi, Alo, H_SZ, Whi + OWR, Wlo + OWR, H_SZ,
        nullptr, R, nullptr, nullptr, H3, H_SZ, H3);

    // 4) gates -> hidden (fp32, into d_out)
    {
        size_t total = (size_t)B_SZ * H_SZ;
        gates_kernel<<<(unsigned)((total + 255) / 256), 256>>>(
            R, prev_y, current_coarse, prev_hidden,
            W_Ic, W_If, bias_u, bias_r, bias_e, hidden);
    }

    // 5) hidden -> bf16 hi/lo (reuse A buffers)
    {
        size_t n = (size_t)B_SZ * H_SZ;
        k_split<<<(unsigned)((n + 255) / 256), 256>>>(hidden, Ahi, Alo, n);
    }

    // 6) heads layer 1: relu(h_half @ W + b) -> t (split bf16, ldc=512 padded)
    gemm_hmma<1><<<dim3(SPAD / 128, B_SZ / 128), 256, SM_TOT>>>(
        Ahi, Alo, H_SZ, Whi + OW1, Wlo + OW1, S_SZ,
        b_O1, nullptr, Thi, Tlo, SPAD, S_SZ, S_SZ);
    gemm_hmma<1><<<dim3(SPAD / 128, B_SZ / 128), 256, SM_TOT>>>(
        Ahi + S_SZ, Alo + S_SZ, H_SZ, Whi + OW3, Wlo + OW3, S_SZ,
        b_O3, nullptr, Thi + TOFF, Tlo + TOFF, SPAD, S_SZ, S_SZ);

    // 7) heads layer 2: t @ W + b -> outputs (fp32)
    gemm_hmma<2><<<dim3(Q_SZ / 128, B_SZ / 128), 256, SM_TOT>>>(
        Thi, Tlo, SPAD, Whi + OW2, Wlo + OW2, S_SZ,
        b_O2, out_coarse, nullptr, nullptr, Q_SZ, S_SZ, Q_SZ);
    gemm_hmma<2><<<dim3(Q_SZ / 128, B_SZ / 128), 256, SM_TOT>>>(
        Thi + TOFF, Tlo + TOFF, SPAD, Whi + OW4, Wlo + OW4, S_SZ,
        b_O4, out_fine, nullptr, nullptr, Q_SZ, S_SZ, Q_SZ);
}

// round 4
// speedup vs baseline: 2.4758x; 1.2275x over previous
#include <cuda_runtime.h>
#include <cuda_bf16.h>
#include <math.h>
#include <stdint.h>

#define B_SZ 32768
#define H_SZ 896
#define S_SZ 448
#define Q_SZ 256
#define H3   2688
#define S3   1344
#define SPAD 512

// ---------------- scratch (device globals; no runtime allocation) ----------
__device__ float          g_R[(size_t)B_SZ * H3];
__device__ __nv_bfloat16  g_Ahi[(size_t)B_SZ * H_SZ];
__device__ __nv_bfloat16  g_Alo[(size_t)B_SZ * H_SZ];
__device__ __nv_bfloat16  g_Thi[2 * (size_t)B_SZ * SPAD];
__device__ __nv_bfloat16  g_Tlo[2 * (size_t)B_SZ * SPAD];

#define OWR 0
#define OW1 (OWR + H3 * H_SZ)
#define OW2 (OW1 + SPAD * S_SZ)
#define OW3 (OW2 + Q_SZ * S_SZ)
#define OW4 (OW3 + SPAD * S_SZ)
#define W_TOTAL (OW4 + Q_SZ * S_SZ)
__device__ __nv_bfloat16  g_Whi[W_TOTAL];
__device__ __nv_bfloat16  g_Wlo[W_TOTAL];

// ---------------- helpers ---------------------------------------------------
__device__ __forceinline__ uint32_t smem_u32(const void* p) {
    uint32_t a;
    asm("{ .reg .u64 t; cvta.to.shared.u64 t, %1; cvt.u32.u64 %0, t; }"
        : "=r"(a) : "l"(p));
    return a;
}
__device__ __forceinline__ void cpa16(uint32_t dst, const void* src) {
    asm volatile("cp.async.cg.shared.global [%0], [%1], 16;\n" :: "r"(dst), "l"(src));
}
__device__ __forceinline__ void ldm_x4(uint32_t* r, uint32_t addr) {
    asm volatile("ldmatrix.sync.aligned.m8n8.x4.shared.b16 {%0,%1,%2,%3}, [%4];"
        : "=r"(r[0]), "=r"(r[1]), "=r"(r[2]), "=r"(r[3]) : "r"(addr));
}
#define MMA(d, a, b) \
    asm volatile("mma.sync.aligned.m16n8k16.row.col.f32.bf16.bf16.f32 " \
        "{%0,%1,%2,%3}, {%4,%5,%6,%7}, {%8,%9}, {%0,%1,%2,%3};" \
        : "+f"((d)[0]), "+f"((d)[1]), "+f"((d)[2]), "+f"((d)[3]) \
        : "r"((a)[0]), "r"((a)[1]), "r"((a)[2]), "r"((a)[3]), \
          "r"((b)[0]), "r"((b)[1]))

// SMEM tile: 128 rows x 32 bf16 cols, pitch 80 B (conflict-free ldmatrix).
#define T_PITCH 80
#define T_BYTES (128 * T_PITCH)          // 10240 per tile
#define ST_BYTES (4 * T_BYTES)           // Ahi,Alo,Bhi,Blo per stage
#define SM_TOT   (2 * ST_BYTES)          // 81920 -> 2 CTAs/SM

// ---------------- split-bf16 HMMA GEMM --------------------------------------
// C = A @ B^T.  A=[M,K] (hi,lo) row-major, B^T=[N,K] (hi,lo) row-major.
// EPI 0: fp32 (no bias)  1: bias+relu -> split bf16  2: bias -> fp32
template<int EPI>
__global__ __launch_bounds__(256, 2)
void gemm_hmma(const __nv_bfloat16* __restrict__ Ahi,
               const __nv_bfloat16* __restrict__ Alo, int lda,
               const __nv_bfloat16* __restrict__ Bhi,
               const __nv_bfloat16* __restrict__ Blo, int ldb,
               const float* __restrict__ bias,
               float* __restrict__ outF,
               __nv_bfloat16* __restrict__ outHi,
               __nv_bfloat16* __restrict__ outLo,
               int ldc, int K, int Nreal)
{
    extern __shared__ char smem[];
    const uint32_t smb = smem_u32(smem);
    const int tid  = threadIdx.x;
    const int wid  = tid >> 5;
    const int lane = tid & 31;
    const int m0 = blockIdx.y * 128;
    const int n0 = blockIdx.x * 128;

    const int wmb = (wid & 1) * 64;   // warp m base (2 warps in m)
    const int wnb = (wid >> 1) * 32;  // warp n base (4 warps in n)

    // cp.async mapping: 2 x 16B per tile per thread
    const int ld_row0 = tid >> 1;
    const int ld_ch0  = (tid & 1) * 2;
    const int g_col0  = ld_ch0 * 8;

    // ldmatrix lane mapping
    const int j  = lane >> 3;
    const int r8 = lane & 7;

    float acc[4][4][4];
#pragma unroll
    for (int mt = 0; mt < 4; mt++)
#pragma unroll
        for (int nt = 0; nt < 4; nt++)
#pragma unroll
            for (int i = 0; i < 4; i++) acc[mt][nt][i] = 0.f;

    const int nc = K >> 5;

    auto load_stage = [&](int c, int st) {
        const int k0 = c << 5;
        const uint32_t sb = smb + st * ST_BYTES;
        const uint32_t so = ld_row0 * T_PITCH + ld_ch0 * 16;
        const __nv_bfloat16* gah = Ahi + (size_t)(m0 + ld_row0) * lda + k0 + g_col0;
        const __nv_bfloat16* gal = Alo + (size_t)(m0 + ld_row0) * lda + k0 + g_col0;
        const __nv_bfloat16* gbh = Bhi + (size_t)(n0 + ld_row0) * ldb + k0 + g_col0;
        const __nv_bfloat16* gbl = Blo + (size_t)(n0 + ld_row0) * ldb + k0 + g_col0;
        cpa16(sb + 0 * T_BYTES + so,      gah);
        cpa16(sb + 0 * T_BYTES + so + 16, gah + 8);
        cpa16(sb + 1 * T_BYTES + so,      gal);
        cpa16(sb + 1 * T_BYTES + so + 16, gal + 8);
        cpa16(sb + 2 * T_BYTES + so,      gbh);
        cpa16(sb + 2 * T_BYTES + so + 16, gbh + 8);
        cpa16(sb + 3 * T_BYTES + so,      gbl);
        cpa16(sb + 3 * T_BYTES + so + 16, gbl + 8);
        asm volatile("cp.async.commit_group;\n" ::: "memory");
    };

    load_stage(0, 0);

    const uint32_t a_row_off = (uint32_t)(wmb + (j & 1) * 8 + r8) * T_PITCH + ((j >> 1) * 8) * 2;
    const uint32_t b_row_off = (uint32_t)(wnb + (j >> 1) * 8 + r8) * T_PITCH + ((j & 1) * 8) * 2;

    for (int c = 0; c < nc; c++) {
        if (c + 1 < nc) {
            load_stage(c + 1, (c + 1) & 1);
            asm volatile("cp.async.wait_group 1;\n" ::: "memory");
        } else {
            asm volatile("cp.async.wait_group 0;\n" ::: "memory");
        }
        __syncthreads();

        const uint32_t sb = smb + (c & 1) * ST_BYTES;
        const uint32_t sAh = sb;
        const uint32_t sAl = sb + T_BYTES;
        const uint32_t sBh = sb + 2 * T_BYTES;
        const uint32_t sBl = sb + 3 * T_BYTES;

#pragma unroll
        for (int ks = 0; ks < 2; ks++) {
            const uint32_t kso = ks * 32;

            uint32_t a[4][4], b1[2][4], b2[2][4];

            // pass 1: Ahi . Bhi
#pragma unroll
            for (int mt = 0; mt < 4; mt++)
                ldm_x4(a[mt], sAh + a_row_off + (uint32_t)mt * 16 * T_PITCH + kso);
#pragma unroll
            for (int p = 0; p < 2; p++)
                ldm_x4(b1[p], sBh + b_row_off + (uint32_t)p * 16 * T_PITCH + kso);
#pragma unroll
            for (int mt = 0; mt < 4; mt++)
#pragma unroll
                for (int nt = 0; nt < 4; nt++)
                    MMA(acc[mt][nt], a[mt], &b1[nt >> 1][(nt & 1) * 2]);

            // pass 2: Ahi . Blo  (b2 dies after this)
#pragma unroll
            for (int p = 0; p < 2; p++)
                ldm_x4(b2[p], sBl + b_row_off + (uint32_t)p * 16 * T_PITCH + kso);
#pragma unroll
            for (int mt = 0; mt < 4; mt++)
#pragma unroll
                for (int nt = 0; nt < 4; nt++)
                    MMA(acc[mt][nt], a[mt], &b2[nt >> 1][(nt & 1) * 2]);

            // pass 3: Alo . Bhi  (a regs reused)
#pragma unroll
            for (int mt = 0; mt < 4; mt++)
                ldm_x4(a[mt], sAl + a_row_off + (uint32_t)mt * 16 * T_PITCH + kso);
#pragma unroll
            for (int mt = 0; mt < 4; mt++)
#pragma unroll
                for (int nt = 0; nt < 4; nt++)
                    MMA(acc[mt][nt], a[mt], &b1[nt >> 1][(nt & 1) * 2]);
        }
        __syncthreads();
    }

    // ---------------- epilogue ----------------
    const int g  = lane >> 2;
    const int tq = lane & 3;
#pragma unroll
    for (int mt = 0; mt < 4; mt++) {
#pragma unroll
        for (int half = 0; half < 2; half++) {
            const size_t m = (size_t)(m0 + wmb + mt * 16 + g + half * 8);
#pragma unroll
            for (int nt = 0; nt < 4; nt++) {
                const int n = n0 + wnb + nt * 8 + 2 * tq;
                if (n < Nreal) {
                    float v0 = acc[mt][nt][half * 2 + 0];
                    float v1 = acc[mt][nt][half * 2 + 1];
                    if (EPI != 0) { v0 += bias[n]; v1 += bias[n + 1]; }
                    if (EPI == 1) {
                        v0 = fmaxf(v0, 0.f); v1 = fmaxf(v1, 0.f);
                        __nv_bfloat16 h0 = __float2bfloat16(v0);
                        __nv_bfloat16 h1 = __float2bfloat16(v1);
                        *reinterpret_cast<__nv_bfloat162*>(outHi + m * ldc + n) =
                            __nv_bfloat162(h0, h1);
                        *reinterpret_cast<__nv_bfloat162*>(outLo + m * ldc + n) =
                            __nv_bfloat162(__float2bfloat16(v0 - __bfloat162float(h0)),
                                           __float2bfloat16(v1 - __bfloat162float(h1)));
                    } else {
                        *reinterpret_cast<float2*>(outF + m * ldc + n) = make_float2(v0, v1);
                    }
                }
            }
        }
    }
}

// ---------------- conversion kernels ----------------------------------------
__global__ void k_split(const float* __restrict__ in,
                        __nv_bfloat16* __restrict__ hi,
                        __nv_bfloat16* __restrict__ lo, size_t n)
{
    size_t i = (size_t)blockIdx.x * blockDim.x + threadIdx.x;
    if (i < n) {
        float f = in[i];
        __nv_bfloat16 h = __float2bfloat16(f);
        hi[i] = h;
        lo[i] = __float2bfloat16(f - __bfloat162float(h));
    }
}

// W[K,N] fp32 -> W^T[Npad,K] bf16 hi/lo, zero-padded rows for n >= N
__global__ void k_splitT(const float* __restrict__ W,
                         __nv_bfloat16* __restrict__ hiT,
                         __nv_bfloat16* __restrict__ loT,
                         int K, int N, int Npad)
{
    int i = blockIdx.x * blockDim.x + threadIdx.x;
    if (i < Npad * K) {
        int n = i / K, k = i % K;
        float f = (n < N) ? W[(size_t)k * N + n] : 0.f;
        __nv_bfloat16 h = __float2bfloat16(f);
        hiT[i] = h;
        loT[i] = __float2bfloat16(f - __bfloat162float(h));
    }
}

// all 4 head weights in one launch (z selects weight)
__global__ void k_splitT4(const float* __restrict__ W1, const float* __restrict__ W2,
                          const float* __restrict__ W3, const float* __restrict__ W4,
                          __nv_bfloat16* __restrict__ hiB,
                          __nv_bfloat16* __restrict__ loB)
{
    const float* W; int N, Npad, off;
    switch (blockIdx.z) {
        case 0:  W = W1; N = S_SZ; Npad = SPAD; off = OW1; break;
        case 1:  W = W2; N = Q_SZ; Npad = Q_SZ; off = OW2; break;
        case 2:  W = W3; N = S_SZ; Npad = SPAD; off = OW3; break;
        default: W = W4; N = Q_SZ; Npad = Q_SZ; off = OW4; break;
    }
    const int K = S_SZ;
    int i = blockIdx.x * blockDim.x + threadIdx.x;
    if (i < Npad * K) {
        int n = i / K, k = i % K;
        float f = (n < N) ? W[(size_t)k * N + n] : 0.f;
        __nv_bfloat16 h = __float2bfloat16(f);
        hiB[off + i] = h;
        loB[off + i] = __float2bfloat16(f - __bfloat162float(h));
    }
}

// ---------------- fused gates (+ bf16 split of hidden) -----------------------
__global__ __launch_bounds__(256)
void gates_kernel(const float* __restrict__ R,
                  const float* __restrict__ prev_y,
                  const float* __restrict__ cc,
                  const float* __restrict__ prev_hidden,
                  const float* __restrict__ W_Ic,
                  const float* __restrict__ W_If,
                  const float* __restrict__ bu,
                  const float* __restrict__ br,
                  const float* __restrict__ be,
                  float* __restrict__ hidden_out,
                  __nv_bfloat16* __restrict__ hhi,
                  __nv_bfloat16* __restrict__ hlo)
{
    const size_t idx = (size_t)blockIdx.x * blockDim.x + threadIdx.x;
    if (idx >= (size_t)B_SZ * H_SZ) return;
    const int b = (int)(idx / H_SZ);
    const int h = (int)(idx % H_SZ);

    const float y0 = prev_y[2 * b];
    const float y1 = prev_y[2 * b + 1];

    float Iu, Ir, Ie;
    if (h < S_SZ) {
        Iu = fmaf(y0, W_Ic[h],            y1 * W_Ic[S3 + h]);
        Ir = fmaf(y0, W_Ic[S_SZ + h],     y1 * W_Ic[S3 + S_SZ + h]);
        Ie = fmaf(y0, W_Ic[2 * S_SZ + h], y1 * W_Ic[S3 + 2 * S_SZ + h]);
    } else {
        const int jj = h - S_SZ;
        const float c = cc[b];
        Iu = fmaf(y0, W_If[jj],            fmaf(y1, W_If[S3 + jj],            c * W_If[2 * S3 + jj]));
        Ir = fmaf(y0, W_If[S_SZ + jj],     fmaf(y1, W_If[S3 + S_SZ + jj],     c * W_If[2 * S3 + S_SZ + jj]));
        Ie = fmaf(y0, W_If[2 * S_SZ + jj], fmaf(y1, W_If[S3 + 2 * S_SZ + jj], c * W_If[2 * S3 + 2 * S_SZ + jj]));
    }

    const size_t rb = (size_t)b * H3;
    const float Ru = R[rb + h];
    const float Rr = R[rb + H_SZ + h];
    const float Re = R[rb + 2 * H_SZ + h];

    const float u = 1.f / (1.f + __expf(-(Ru + Iu + bu[h])));
    const float r = 1.f / (1.f + __expf(-(Rr + Ir + br[h])));
    const float e = tanhf(fmaf(r, Re, Ie + be[h]));

    const float ph = prev_hidden[idx];
    const float hv = fmaf(u, ph - e, e);
    hidden_out[idx] = hv;
    __nv_bfloat16 hb = __float2bfloat16(hv);
    hhi[idx] = hb;
    hlo[idx] = __float2bfloat16(hv - __bfloat162float(hb));
}

// ---------------- launch -------------------------------------------------------
extern "C" void kernel_launch(void* const* d_in, const int* in_sizes, int n_in,
                              void* d_out, int out_size)
{
    const float* prev_y         = (const float*)d_in[0];
    const float* prev_hidden    = (const float*)d_in[1];
    const float* current_coarse = (const float*)d_in[2];
    const float* W_R            = (const float*)d_in[3];
    const float* W_Ic           = (const float*)d_in[4];
    const float* W_If           = (const float*)d_in[5];
    const float* W_O1           = (const float*)d_in[6];
    const float* b_O1           = (const float*)d_in[7];
    const float* W_O2           = (const float*)d_in[8];
    const float* b_O2           = (const float*)d_in[9];
    const float* W_O3           = (const float*)d_in[10];
    const float* b_O3           = (const float*)d_in[11];
    const float* W_O4           = (const float*)d_in[12];
    const float* b_O4           = (const float*)d_in[13];
    const float* bias_u         = (const float*)d_in[14];
    const float* bias_r         = (const float*)d_in[15];
    const float* bias_e         = (const float*)d_in[16];

    float* out        = (float*)d_out;
    float* out_coarse = out;
    float* out_fine   = out + (size_t)B_SZ * Q_SZ;
    float* hidden     = out + 2 * (size_t)B_SZ * Q_SZ;

    float*         R;   cudaGetSymbolAddress((void**)&R,   g_R);
    __nv_bfloat16* Ahi; cudaGetSymbolAddress((void**)&Ahi, g_Ahi);
    __nv_bfloat16* Alo; cudaGetSymbolAddress((void**)&Alo, g_Alo);
    __nv_bfloat16* Thi; cudaGetSymbolAddress((void**)&Thi, g_Thi);
    __nv_bfloat16* Tlo; cudaGetSymbolAddress((void**)&Tlo, g_Tlo);
    __nv_bfloat16* Whi; cudaGetSymbolAddress((void**)&Whi, g_Whi);
    __nv_bfloat16* Wlo; cudaGetSymbolAddress((void**)&Wlo, g_Wlo);

    cudaFuncSetAttribute(gemm_hmma<0>, cudaFuncAttributeMaxDynamicSharedMemorySize, SM_TOT);
    cudaFuncSetAttribute(gemm_hmma<1>, cudaFuncAttributeMaxDynamicSharedMemorySize, SM_TOT);
    cudaFuncSetAttribute(gemm_hmma<2>, cudaFuncAttributeMaxDynamicSharedMemorySize, SM_TOT);

    const size_t TOFF = (size_t)B_SZ * SPAD;

    // 0) W_R conversion
    {
        int n = H3 * H_SZ;
        k_splitT<<<(n + 255) / 256, 256>>>(W_R, Whi + OWR, Wlo + OWR, H_SZ, H3, H3);
    }
    // 1) prev_hidden -> bf16 hi/lo
    {
        size_t n = (size_t)B_SZ * H_SZ;
        k_split<<<(unsigned)((n + 255) / 256), 256>>>(prev_hidden, Ahi, Alo, n);
    }
    // 2) R = prev_hidden @ W_R
    gemm_hmma<0><<<dim3(H3 / 128, B_SZ / 128), 256, SM_TOT>>>(
        Ahi, Alo, H_SZ, Whi + OWR, Wlo + OWR, H_SZ,
        nullptr, R, nullptr, nullptr, H3, H_SZ, H3);
    // 3) gates -> hidden (fp32 in d_out) + bf16 split (reuse A buffers)
    {
        size_t total = (size_t)B_SZ * H_SZ;
        gates_kernel<<<(unsigned)((total + 255) / 256), 256>>>(
            R, prev_y, current_coarse, prev_hidden,
            W_Ic, W_If, bias_u, bias_r, bias_e, hidden, Ahi, Alo);
    }
    // 4) head weight conversions (single launch)
    {
        int n = SPAD * S_SZ;
        dim3 g((n + 255) / 256, 1, 4);
        k_splitT4<<<g, 256>>>(W_O1, W_O2, W_O3, W_O4, Whi, Wlo);
    }
    // 5/6) head layer 1: relu(h_half @ W + b) -> t (split bf16, ldc=512)
    gemm_hmma<1><<<dim3(SPAD / 128, B_SZ / 128), 256, SM_TOT>>>(
        Ahi, Alo, H_SZ, Whi + OW1, Wlo + OW1, S_SZ,
        b_O1, nullptr, Thi, Tlo, SPAD, S_SZ, S_SZ);
    gemm_hmma<1><<<dim3(SPAD / 128, B_SZ / 128), 256, SM_TOT>>>(
        Ahi + S_SZ, Alo + S_SZ, H_SZ, Whi + OW3, Wlo + OW3, S_SZ,
        b_O3, nullptr, Thi + TOFF, Tlo + TOFF, SPAD, S_SZ, S_SZ);
    // 7/8) head layer 2: t @ W + b -> outputs (fp32)
    gemm_hmma<2><<<dim3(Q_SZ / 128, B_SZ / 128), 256, SM_TOT>>>(
        Thi, Tlo, SPAD, Whi + OW2, Wlo + OW2, S_SZ,
        b_O2, out_coarse, nullptr, nullptr, Q_SZ, S_SZ, Q_SZ);
    gemm_hmma<2><<<dim3(Q_SZ / 128, B_SZ / 128), 256, SM_TOT>>>(
        Thi + TOFF, Tlo + TOFF, SPAD, Whi + OW4, Wlo + OW4, S_SZ,
        b_O4, out_fine, nullptr, nullptr, Q_SZ, S_SZ, Q_SZ);
}

// round 5
// speedup vs baseline: 2.4780x; 1.0009x over previous
#include <cuda_runtime.h>
#include <cuda_bf16.h>
#include <math.h>
#include <stdint.h>

#define B_SZ 32768
#define H_SZ 896
#define S_SZ 448
#define Q_SZ 256
#define H3   2688
#define S3   1344
#define SPAD 512

// ---------------- scratch (device globals; no runtime allocation) ----------
__device__ float          g_R[(size_t)B_SZ * H3];
__device__ __nv_bfloat16  g_Ahi[(size_t)B_SZ * H_SZ];
__device__ __nv_bfloat16  g_Alo[(size_t)B_SZ * H_SZ];
__device__ __nv_bfloat16  g_Thi[2 * (size_t)B_SZ * SPAD];
__device__ __nv_bfloat16  g_Tlo[2 * (size_t)B_SZ * SPAD];

#define OWR 0
#define OW1 (OWR + H3 * H_SZ)
#define OW2 (OW1 + SPAD * S_SZ)
#define OW3 (OW2 + Q_SZ * S_SZ)
#define OW4 (OW3 + SPAD * S_SZ)
#define W_TOTAL (OW4 + Q_SZ * S_SZ)
__device__ __nv_bfloat16  g_Whi[W_TOTAL];
__device__ __nv_bfloat16  g_Wlo[W_TOTAL];

// ---------------- helpers ---------------------------------------------------
__device__ __forceinline__ uint32_t smem_u32(const void* p) {
    uint32_t a;
    asm("{ .reg .u64 t; cvta.to.shared.u64 t, %1; cvt.u32.u64 %0, t; }"
        : "=r"(a) : "l"(p));
    return a;
}
__device__ __forceinline__ void cpa16(uint32_t dst, const void* src) {
    asm volatile("cp.async.cg.shared.global [%0], [%1], 16;\n" :: "r"(dst), "l"(src));
}
__device__ __forceinline__ void ldm_x4(uint32_t* r, uint32_t addr) {
    asm volatile("ldmatrix.sync.aligned.m8n8.x4.shared.b16 {%0,%1,%2,%3}, [%4];"
        : "=r"(r[0]), "=r"(r[1]), "=r"(r[2]), "=r"(r[3]) : "r"(addr));
}
#define MMA(d, a, b) \
    asm volatile("mma.sync.aligned.m16n8k16.row.col.f32.bf16.bf16.f32 " \
        "{%0,%1,%2,%3}, {%4,%5,%6,%7}, {%8,%9}, {%0,%1,%2,%3};" \
        : "+f"((d)[0]), "+f"((d)[1]), "+f"((d)[2]), "+f"((d)[3]) \
        : "r"((a)[0]), "r"((a)[1]), "r"((a)[2]), "r"((a)[3]), \
          "r"((b)[0]), "r"((b)[1]))

// SMEM tile: 128 rows x 32 bf16 cols, pitch 80 B (conflict-free ldmatrix).
#define T_PITCH 80
#define T_BYTES (128 * T_PITCH)          // 10240 per tile
#define ST_BYTES (4 * T_BYTES)           // Ahi,Alo,Bhi,Blo per stage
#define SM_TOT   (2 * ST_BYTES)          // 81920 -> 2 CTAs/SM

// ---------------- split-bf16 HMMA GEMM --------------------------------------
// C = A @ B^T.  A=[M,K] (hi,lo) row-major, B^T=[N,K] (hi,lo) row-major.
// EPI 0: fp32 (no bias)  1: bias+relu -> split bf16  2: bias -> fp32
template<int EPI>
__global__ __launch_bounds__(256, 2)
void gemm_hmma(const __nv_bfloat16* __restrict__ Ahi,
               const __nv_bfloat16* __restrict__ Alo, int lda,
               const __nv_bfloat16* __restrict__ Bhi,
               const __nv_bfloat16* __restrict__ Blo, int ldb,
               const float* __restrict__ bias,
               float* __restrict__ outF,
               __nv_bfloat16* __restrict__ outHi,
               __nv_bfloat16* __restrict__ outLo,
               int ldc, int K, int Nreal)
{
    extern __shared__ char smem[];
    const uint32_t smb = smem_u32(smem);
    const int tid  = threadIdx.x;
    const int wid  = tid >> 5;
    const int lane = tid & 31;
    const int m0 = blockIdx.y * 128;
    const int n0 = blockIdx.x * 128;

    const int wmb = (wid & 1) * 64;   // warp m base (2 warps in m)
    const int wnb = (wid >> 1) * 32;  // warp n base (4 warps in n)

    // cp.async mapping: 2 x 16B per tile per thread
    const int ld_row0 = tid >> 1;
    const int ld_ch0  = (tid & 1) * 2;
    const int g_col0  = ld_ch0 * 8;

    // ldmatrix lane mapping
    const int j  = lane >> 3;
    const int r8 = lane & 7;

    float acc[4][4][4];
#pragma unroll
    for (int mt = 0; mt < 4; mt++)
#pragma unroll
        for (int nt = 0; nt < 4; nt++)
#pragma unroll
            for (int i = 0; i < 4; i++) acc[mt][nt][i] = 0.f;

    const int nc = K >> 5;

    auto load_stage = [&](int c, int st) {
        const int k0 = c << 5;
        const uint32_t sb = smb + st * ST_BYTES;
        const uint32_t so = ld_row0 * T_PITCH + ld_ch0 * 16;
        const __nv_bfloat16* gah = Ahi + (size_t)(m0 + ld_row0) * lda + k0 + g_col0;
        const __nv_bfloat16* gal = Alo + (size_t)(m0 + ld_row0) * lda + k0 + g_col0;
        const __nv_bfloat16* gbh = Bhi + (size_t)(n0 + ld_row0) * ldb + k0 + g_col0;
        const __nv_bfloat16* gbl = Blo + (size_t)(n0 + ld_row0) * ldb + k0 + g_col0;
        cpa16(sb + 0 * T_BYTES + so,      gah);
        cpa16(sb + 0 * T_BYTES + so + 16, gah + 8);
        cpa16(sb + 1 * T_BYTES + so,      gal);
        cpa16(sb + 1 * T_BYTES + so + 16, gal + 8);
        cpa16(sb + 2 * T_BYTES + so,      gbh);
        cpa16(sb + 2 * T_BYTES + so + 16, gbh + 8);
        cpa16(sb + 3 * T_BYTES + so,      gbl);
        cpa16(sb + 3 * T_BYTES + so + 16, gbl + 8);
        asm volatile("cp.async.commit_group;\n" ::: "memory");
    };

    load_stage(0, 0);

    const uint32_t a_row_off = (uint32_t)(wmb + (j & 1) * 8 + r8) * T_PITCH + ((j >> 1) * 8) * 2;
    const uint32_t b_row_off = (uint32_t)(wnb + (j >> 1) * 8 + r8) * T_PITCH + ((j & 1) * 8) * 2;

    for (int c = 0; c < nc; c++) {
        if (c + 1 < nc) {
            load_stage(c + 1, (c + 1) & 1);
            asm volatile("cp.async.wait_group 1;\n" ::: "memory");
        } else {
            asm volatile("cp.async.wait_group 0;\n" ::: "memory");
        }
        __syncthreads();

        const uint32_t sb = smb + (c & 1) * ST_BYTES;
        const uint32_t sAh = sb;
        const uint32_t sAl = sb + T_BYTES;
        const uint32_t sBh = sb + 2 * T_BYTES;
        const uint32_t sBl = sb + 3 * T_BYTES;

#pragma unroll
        for (int ks = 0; ks < 2; ks++) {
            const uint32_t kso = ks * 32;

            uint32_t a[4][4], b1[2][4], b2[2][4];

            // pass 1: Ahi . Bhi
#pragma unroll
            for (int mt = 0; mt < 4; mt++)
                ldm_x4(a[mt], sAh + a_row_off + (uint32_t)mt * 16 * T_PITCH + kso);
#pragma unroll
            for (int p = 0; p < 2; p++)
                ldm_x4(b1[p], sBh + b_row_off + (uint32_t)p * 16 * T_PITCH + kso);
#pragma unroll
            for (int mt = 0; mt < 4; mt++)
#pragma unroll
                for (int nt = 0; nt < 4; nt++)
                    MMA(acc[mt][nt], a[mt], &b1[nt >> 1][(nt & 1) * 2]);

            // pass 2: Ahi . Blo  (b2 dies after this)
#pragma unroll
            for (int p = 0; p < 2; p++)
                ldm_x4(b2[p], sBl + b_row_off + (uint32_t)p * 16 * T_PITCH + kso);
#pragma unroll
            for (int mt = 0; mt < 4; mt++)
#pragma unroll
                for (int nt = 0; nt < 4; nt++)
                    MMA(acc[mt][nt], a[mt], &b2[nt >> 1][(nt & 1) * 2]);

            // pass 3: Alo . Bhi  (a regs reused)
#pragma unroll
            for (int mt = 0; mt < 4; mt++)
                ldm_x4(a[mt], sAl + a_row_off + (uint32_t)mt * 16 * T_PITCH + kso);
#pragma unroll
            for (int mt = 0; mt < 4; mt++)
#pragma unroll
                for (int nt = 0; nt < 4; nt++)
                    MMA(acc[mt][nt], a[mt], &b1[nt >> 1][(nt & 1) * 2]);
        }
        __syncthreads();
    }

    // ---------------- epilogue ----------------
    const int g  = lane >> 2;
    const int tq = lane & 3;
#pragma unroll
    for (int mt = 0; mt < 4; mt++) {
#pragma unroll
        for (int half = 0; half < 2; half++) {
            const size_t m = (size_t)(m0 + wmb + mt * 16 + g + half * 8);
#pragma unroll
            for (int nt = 0; nt < 4; nt++) {
                const int n = n0 + wnb + nt * 8 + 2 * tq;
                if (n < Nreal) {
                    float v0 = acc[mt][nt][half * 2 + 0];
                    float v1 = acc[mt][nt][half * 2 + 1];
                    if (EPI != 0) { v0 += bias[n]; v1 += bias[n + 1]; }
                    if (EPI == 1) {
                        v0 = fmaxf(v0, 0.f); v1 = fmaxf(v1, 0.f);
                        __nv_bfloat16 h0 = __float2bfloat16(v0);
                        __nv_bfloat16 h1 = __float2bfloat16(v1);
                        *reinterpret_cast<__nv_bfloat162*>(outHi + m * ldc + n) =
                            __nv_bfloat162(h0, h1);
                        *reinterpret_cast<__nv_bfloat162*>(outLo + m * ldc + n) =
                            __nv_bfloat162(__float2bfloat16(v0 - __bfloat162float(h0)),
                                           __float2bfloat16(v1 - __bfloat162float(h1)));
                    } else {
                        *reinterpret_cast<float2*>(outF + m * ldc + n) = make_float2(v0, v1);
                    }
                }
            }
        }
    }
}

// ---------------- conversion kernels ----------------------------------------
__global__ void k_split(const float* __restrict__ in,
                        __nv_bfloat16* __restrict__ hi,
                        __nv_bfloat16* __restrict__ lo, size_t n)
{
    size_t i = (size_t)blockIdx.x * blockDim.x + threadIdx.x;
    if (i < n) {
        float f = in[i];
        __nv_bfloat16 h = __float2bfloat16(f);
        hi[i] = h;
        lo[i] = __float2bfloat16(f - __bfloat162float(h));
    }
}

// W[K,N] fp32 -> W^T[Npad,K] bf16 hi/lo, zero-padded rows for n >= N
__global__ void k_splitT(const float* __restrict__ W,
                         __nv_bfloat16* __restrict__ hiT,
                         __nv_bfloat16* __restrict__ loT,
                         int K, int N, int Npad)
{
    int i = blockIdx.x * blockDim.x + threadIdx.x;
    if (i < Npad * K) {
        int n = i / K, k = i % K;
        float f = (n < N) ? W[(size_t)k * N + n] : 0.f;
        __nv_bfloat16 h = __float2bfloat16(f);
        hiT[i] = h;
        loT[i] = __float2bfloat16(f - __bfloat162float(h));
    }
}

// all 4 head weights in one launch (z selects weight)
__global__ void k_splitT4(const float* __restrict__ W1, const float* __restrict__ W2,
                          const float* __restrict__ W3, const float* __restrict__ W4,
                          __nv_bfloat16* __restrict__ hiB,
                          __nv_bfloat16* __restrict__ loB)
{
    const float* W; int N, Npad, off;
    switch (blockIdx.z) {
        case 0:  W = W1; N = S_SZ; Npad = SPAD; off = OW1; break;
        case 1:  W = W2; N = Q_SZ; Npad = Q_SZ; off = OW2; break;
        case 2:  W = W3; N = S_SZ; Npad = SPAD; off = OW3; break;
        default: W = W4; N = Q_SZ; Npad = Q_SZ; off = OW4; break;
    }
    const int K = S_SZ;
    int i = blockIdx.x * blockDim.x + threadIdx.x;
    if (i < Npad * K) {
        int n = i / K, k = i % K;
        float f = (n < N) ? W[(size_t)k * N + n] : 0.f;
        __nv_bfloat16 h = __float2bfloat16(f);
        hiB[off + i] = h;
        loB[off + i] = __float2bfloat16(f - __bfloat162float(h));
    }
}

// ---------------- fused gates (+ bf16 split of hidden) -----------------------
__global__ __launch_bounds__(256)
void gates_kernel(const float* __restrict__ R,
                  const float* __restrict__ prev_y,
                  const float* __restrict__ cc,
                  const float* __restrict__ prev_hidden,
                  const float* __restrict__ W_Ic,
                  const float* __restrict__ W_If,
                  const float* __restrict__ bu,
                  const float* __restrict__ br,
                  const float* __restrict__ be,
                  float* __restrict__ hidden_out,
                  __nv_bfloat16* __restrict__ hhi,
                  __nv_bfloat16* __restrict__ hlo)
{
    const size_t idx = (size_t)blockIdx.x * blockDim.x + threadIdx.x;
    if (idx >= (size_t)B_SZ * H_SZ) return;
    const int b = (int)(idx / H_SZ);
    const int h = (int)(idx % H_SZ);

    const float y0 = prev_y[2 * b];
    const float y1 = prev_y[2 * b + 1];

    float Iu, Ir, Ie;
    if (h < S_SZ) {
        Iu = fmaf(y0, W_Ic[h],            y1 * W_Ic[S3 + h]);
        Ir = fmaf(y0, W_Ic[S_SZ + h],     y1 * W_Ic[S3 + S_SZ + h]);
        Ie = fmaf(y0, W_Ic[2 * S_SZ + h], y1 * W_Ic[S3 + 2 * S_SZ + h]);
    } else {
        const int jj = h - S_SZ;
        const float c = cc[b];
        Iu = fmaf(y0, W_If[jj],            fmaf(y1, W_If[S3 + jj],            c * W_If[2 * S3 + jj]));
        Ir = fmaf(y0, W_If[S_SZ + jj],     fmaf(y1, W_If[S3 + S_SZ + jj],     c * W_If[2 * S3 + S_SZ + jj]));
        Ie = fmaf(y0, W_If[2 * S_SZ + jj], fmaf(y1, W_If[S3 + 2 * S_SZ + jj], c * W_If[2 * S3 + 2 * S_SZ + jj]));
    }

    const size_t rb = (size_t)b * H3;
    const float Ru = R[rb + h];
    const float Rr = R[rb + H_SZ + h];
    const float Re = R[rb + 2 * H_SZ + h];

    const float u = 1.f / (1.f + __expf(-(Ru + Iu + bu[h])));
    const float r = 1.f / (1.f + __expf(-(Rr + Ir + br[h])));
    const float e = tanhf(fmaf(r, Re, Ie + be[h]));

    const float ph = prev_hidden[idx];
    const float hv = fmaf(u, ph - e, e);
    hidden_out[idx] = hv;
    __nv_bfloat16 hb = __float2bfloat16(hv);
    hhi[idx] = hb;
    hlo[idx] = __float2bfloat16(hv - __bfloat162float(hb));
}

// ---------------- launch -------------------------------------------------------
extern "C" void kernel_launch(void* const* d_in, const int* in_sizes, int n_in,
                              void* d_out, int out_size)
{
    const float* prev_y         = (const float*)d_in[0];
    const float* prev_hidden    = (const float*)d_in[1];
    const float* current_coarse = (const float*)d_in[2];
    const float* W_R            = (const float*)d_in[3];
    const float* W_Ic           = (const float*)d_in[4];
    const float* W_If           = (const float*)d_in[5];
    const float* W_O1           = (const float*)d_in[6];
    const float* b_O1           = (const float*)d_in[7];
    const float* W_O2           = (const float*)d_in[8];
    const float* b_O2           = (const float*)d_in[9];
    const float* W_O3           = (const float*)d_in[10];
    const float* b_O3           = (const float*)d_in[11];
    const float* W_O4           = (const float*)d_in[12];
    const float* b_O4           = (const float*)d_in[13];
    const float* bias_u         = (const float*)d_in[14];
    const float* bias_r         = (const float*)d_in[15];
    const float* bias_e         = (const float*)d_in[16];

    float* out        = (float*)d_out;
    float* out_coarse = out;
    float* out_fine   = out + (size_t)B_SZ * Q_SZ;
    float* hidden     = out + 2 * (size_t)B_SZ * Q_SZ;

    float*         R;   cudaGetSymbolAddress((void**)&R,   g_R);
    __nv_bfloat16* Ahi; cudaGetSymbolAddress((void**)&Ahi, g_Ahi);
    __nv_bfloat16* Alo; cudaGetSymbolAddress((void**)&Alo, g_Alo);
    __nv_bfloat16* Thi; cudaGetSymbolAddress((void**)&Thi, g_Thi);
    __nv_bfloat16* Tlo; cudaGetSymbolAddress((void**)&Tlo, g_Tlo);
    __nv_bfloat16* Whi; cudaGetSymbolAddress((void**)&Whi, g_Whi);
    __nv_bfloat16* Wlo; cudaGetSymbolAddress((void**)&Wlo, g_Wlo);

    cudaFuncSetAttribute(gemm_hmma<0>, cudaFuncAttributeMaxDynamicSharedMemorySize, SM_TOT);
    cudaFuncSetAttribute(gemm_hmma<1>, cudaFuncAttributeMaxDynamicSharedMemorySize, SM_TOT);
    cudaFuncSetAttribute(gemm_hmma<2>, cudaFuncAttributeMaxDynamicSharedMemorySize, SM_TOT);

    const size_t TOFF = (size_t)B_SZ * SPAD;

    // 0) W_R conversion
    {
        int n = H3 * H_SZ;
        k_splitT<<<(n + 255) / 256, 256>>>(W_R, Whi + OWR, Wlo + OWR, H_SZ, H3, H3);
    }
    // 1) prev_hidden -> bf16 hi/lo
    {
        size_t n = (size_t)B_SZ * H_SZ;
        k_split<<<(unsigned)((n + 255) / 256), 256>>>(prev_hidden, Ahi, Alo, n);
    }
    // 2) R = prev_hidden @ W_R
    gemm_hmma<0><<<dim3(H3 / 128, B_SZ / 128), 256, SM_TOT>>>(
        Ahi, Alo, H_SZ, Whi + OWR, Wlo + OWR, H_SZ,
        nullptr, R, nullptr, nullptr, H3, H_SZ, H3);
    // 3) gates -> hidden (fp32 in d_out) + bf16 split (reuse A buffers)
    {
        size_t total = (size_t)B_SZ * H_SZ;
        gates_kernel<<<(unsigned)((total + 255) / 256), 256>>>(
            R, prev_y, current_coarse, prev_hidden,
            W_Ic, W_If, bias_u, bias_r, bias_e, hidden, Ahi, Alo);
    }
    // 4) head weight conversions (single launch)
    {
        int n = SPAD * S_SZ;
        dim3 g((n + 255) / 256, 1, 4);
        k_splitT4<<<g, 256>>>(W_O1, W_O2, W_O3, W_O4, Whi, Wlo);
    }
    // 5/6) head layer 1: relu(h_half @ W + b) -> t (split bf16, ldc=512)
    gemm_hmma<1><<<dim3(SPAD / 128, B_SZ / 128), 256, SM_TOT>>>(
        Ahi, Alo, H_SZ, Whi + OW1, Wlo + OW1, S_SZ,
        b_O1, nullptr, Thi, Tlo, SPAD, S_SZ, S_SZ);
    gemm_hmma<1><<<dim3(SPAD / 128, B_SZ / 128), 256, SM_TOT>>>(
        Ahi + S_SZ, Alo + S_SZ, H_SZ, Whi + OW3, Wlo + OW3, S_SZ,
        b_O3, nullptr, Thi + TOFF, Tlo + TOFF, SPAD, S_SZ, S_SZ);
    // 7/8) head layer 2: t @ W + b -> outputs (fp32)
    gemm_hmma<2><<<dim3(Q_SZ / 128, B_SZ / 128), 256, SM_TOT>>>(
        Thi, Tlo, SPAD, Whi + OW2, Wlo + OW2, S_SZ,
        b_O2, out_coarse, nullptr, nullptr, Q_SZ, S_SZ, Q_SZ);
    gemm_hmma<2><<<dim3(Q_SZ / 128, B_SZ / 128), 256, SM_TOT>>>(
        Thi + TOFF, Tlo + TOFF, SPAD, Whi + OW4, Wlo + OW4, S_SZ,
        b_O4, out_fine, nullptr, nullptr, Q_SZ, S_SZ, Q_SZ);
}